// round 8
// baseline (speedup 1.0000x reference)
#include <cuda_runtime.h>

#define BB 16
#define KK 512
#define DD 256
#define TT 4096
#define TTILE 128          // frames per block
#define DHALF 128          // d-rows per block (D split over grid.z)
#define NWARP 8
#define THREADS 256
#define DPW (DHALF / NWARP)  // 16 d-rows per warp
#define SPAN 64            // max block k-range staged
#define SPANP 80           // sPh row pitch: SPAN + WMAX zero-pad
#define WMAX 16            // max per-frame softmax window kept
#define WREG 8             // weight j-slots held in registers
#define WP 132             // sW row pitch (floats): 16B multiple + bank offset
#define THRESH 25.0f       // keep terms with weight ratio > e^-25

__device__ float g_centers[BB * KK];

// Exact sequential fp32 cumsum per batch (matches reference rounding).
__global__ void __launch_bounds__(512) centers_kernel(const float* __restrict__ dur) {
    __shared__ float sD[BB * 513];
    for (int i = threadIdx.x; i < BB * KK; i += 512) {
        int bb = i >> 9, k = i & (KK - 1);
        sD[bb * 513 + k] = dur[i];
    }
    __syncthreads();
    int b = threadIdx.x;
    if (b < BB) {
        const float* d = sD + b * 513;
        float* c = g_centers + b * KK;
        float s = 0.0f;
        #pragma unroll 8
        for (int k = 0; k < KK; ++k) {
            float dk = d[k];
            s += dk;                        // strictly sequential association
            c[k] = s - 0.5f * dk;
        }
    }
}

__global__ void __launch_bounds__(THREADS, 2) upsample_kernel(
    const float* __restrict__ phoneme,   // (B, D, K)
    const float* __restrict__ frame,     // (B, D, T)
    float* __restrict__ out)             // (B, D, T)
{
    extern __shared__ __align__(16) float sm[];
    float* sC  = sm;                              // KK
    float* sW  = sC + KK;                         // WMAX * WP
    float* sPh = sW + WMAX * WP;                  // DHALF * SPANP
    int* sKmn  = (int*)(sPh + DHALF * SPANP);     // TTILE
    int* sWid  = sKmn + TTILE;                    // TTILE
    int* sKb   = sWid + TTILE;                    // 2

    const int b     = blockIdx.y;
    const int t0    = blockIdx.x * TTILE;
    const int dbase = blockIdx.z * DHALF;
    const int tid   = threadIdx.x;
    const int lane  = tid & 31;
    const int warp  = tid >> 5;

    if (tid == 0) { sKb[0] = KK; sKb[1] = 0; }
    for (int i = tid; i < KK; i += THREADS) sC[i] = g_centers[b * KK + i];
    for (int i = tid; i < WMAX * WP; i += THREADS) sW[i] = 0.0f;
    __syncthreads();

    // ---- phase 1: binary-search window + windowed softmax (1 thread / frame) ----
    if (tid < TTILE) {
        const int tt = tid;
        const float tc = (float)(t0 + tt) + 0.5f;
        int pos = 0;                          // count of centers < tc (ascending)
        #pragma unroll
        for (int step = 256; step; step >>= 1) {
            int np = pos + step;
            if (np <= KK && sC[np - 1] < tc) pos = np;
        }
        int ka = pos > 0 ? pos - 1 : 0;
        int kz = pos < KK ? pos : KK - 1;
        float da = fabsf(tc - sC[ka]);
        float db = fabsf(tc - sC[kz]);
        int kc; float dmin;
        if (da <= db) { kc = ka; dmin = da; } else { kc = kz; dmin = db; }
        const float m = -(dmin * dmin);       // max energy (dist^2 unimodal in k)
        const float nthr = m - THRESH;
        int kmn = kc, kmx = kc;
        while (kmn > 0) {
            float df = tc - sC[kmn - 1];
            if (-(df * df) > nthr) --kmn; else break;
        }
        while (kmx < KK - 1) {
            float df = tc - sC[kmx + 1];
            if (-(df * df) > nthr) ++kmx; else break;
        }
        int wid = kmx - kmn + 1;
        if (wid > WMAX) wid = WMAX;
        float sum = 0.0f;
        for (int j = 0; j < wid; ++j) {
            float df = tc - sC[kmn + j];
            float x = __expf(-(df * df) - m);
            sW[j * WP + tt] = x;
            sum += x;
        }
        const float inv = 1.0f / sum;
        for (int j = 0; j < wid; ++j) sW[j * WP + tt] *= inv;
        sKmn[tt] = kmn;
        sWid[tt] = wid;
        atomicMin(&sKb[0], kmn);
        atomicMax(&sKb[1], kmx);
    }
    __syncthreads();

    const int kb = sKb[0];
    int span = sKb[1] - kb + 1;
    if (span > SPAN) span = SPAN;   // safety clamp (never triggers here)

    // ---- phase 2: bulk-stage block's phoneme panel (coalesced, high MLP) ----
    for (int r = warp; r < DHALF; r += NWARP) {
        const float* prow = phoneme + ((size_t)b * DD + dbase + r) * KK + kb;
        int c0 = lane, c1 = lane + 32;
        sPh[r * SPANP + c0] = (c0 < span) ? prow[c0] : 0.0f;
        sPh[r * SPANP + c1] = (c1 < span) ? prow[c1] : 0.0f;
        if (lane < SPANP - SPAN) sPh[r * SPANP + SPAN + lane] = 0.0f;
    }
    __syncthreads();

    // ---- phase 3: weights in REGISTERS, streamed frame/out, smem phoneme ----
    const int tbase = 4 * lane;
    const int q0 = min(sKmn[tbase + 0] - kb, SPAN - 1);
    const int q1 = min(sKmn[tbase + 1] - kb, SPAN - 1);
    const int q2 = min(sKmn[tbase + 2] - kb, SPAN - 1);
    const int q3 = min(sKmn[tbase + 3] - kb, SPAN - 1);
    const int wm = max(max(sWid[tbase], sWid[tbase + 1]),
                       max(sWid[tbase + 2], sWid[tbase + 3]));

    // hoist first WREG weight rows into registers (loaded once, reused 16x)
    float4 wr[WREG];
    #pragma unroll
    for (int j = 0; j < WREG; ++j)
        wr[j] = *(const float4*)(sW + j * WP + tbase);

    const int dw = warp * DPW;
    const size_t fo = ((size_t)b * DD + dbase) * TT + t0 + tbase;
    const float* frp = frame + fo;
    float* op = out + fo;

    // depth-2 frame prefetch pipeline
    float4 fA = *(const float4*)(frp + (size_t)dw * TT);
    float4 fB = *(const float4*)(frp + (size_t)(dw + 1) * TT);

    #pragma unroll 1
    for (int i = 0; i < DPW; ++i) {
        const float* pr = sPh + (dw + i) * SPANP;
        float4 fcur = fA;
        fA = fB;
        if (i + 2 < DPW)
            fB = *(const float4*)(frp + (size_t)(dw + i + 2) * TT);

        float sx = 0.0f, sy = 0.0f, sz = 0.0f, sw = 0.0f;
        #pragma unroll
        for (int j = 0; j < WREG; ++j) {
            sx = fmaf(wr[j].x, pr[q0 + j], sx);
            sy = fmaf(wr[j].y, pr[q1 + j], sy);
            sz = fmaf(wr[j].z, pr[q2 + j], sz);
            sw = fmaf(wr[j].w, pr[q3 + j], sw);
        }
        // rare tail: windows wider than WREG (weights identical to smem table)
        for (int j = WREG; j < wm; ++j) {
            float4 w4 = *(const float4*)(sW + j * WP + tbase);
            sx = fmaf(w4.x, pr[q0 + j], sx);
            sy = fmaf(w4.y, pr[q1 + j], sy);
            sz = fmaf(w4.z, pr[q2 + j], sz);
            sw = fmaf(w4.w, pr[q3 + j], sw);
        }
        *(float4*)(op + (size_t)(dw + i) * TT) =
            make_float4(fcur.x + sx, fcur.y + sy, fcur.z + sz, fcur.w + sw);
    }
}

extern "C" void kernel_launch(void* const* d_in, const int* in_sizes, int n_in,
                              void* d_out, int out_size) {
    const float* durations = (const float*)d_in[0];  // (B, K)
    const float* phoneme   = (const float*)d_in[1];  // (B, D, K)
    const float* frame     = (const float*)d_in[2];  // (B, D, T)
    float* out = (float*)d_out;                      // (B, D, T)

    centers_kernel<<<1, 512>>>(durations);

    size_t smem = (size_t)(KK + WMAX * WP + DHALF * SPANP) * sizeof(float)
                + (size_t)(2 * TTILE + 2) * sizeof(int);
    cudaFuncSetAttribute(upsample_kernel,
                         cudaFuncAttributeMaxDynamicSharedMemorySize, (int)smem);
    dim3 grid(TT / TTILE, BB, DD / DHALF);
    upsample_kernel<<<grid, THREADS, smem>>>(phoneme, frame, out);
}

// round 9
// speedup vs baseline: 1.4584x; 1.4584x over previous
#include <cuda_runtime.h>

#define BB 16
#define KK 512
#define DD 256
#define TT 4096
#define TTILE 128          // frames per block
#define DHALF 128          // d-rows per block (D split over grid.z)
#define THREADS 256
#define SPAN 64            // max block k-range staged
#define SPANP 80           // sPh row pitch: SPAN + WMAX zero-pad
#define WMAX 16            // max per-frame softmax window kept
#define WP2 20             // sW2 row pitch (floats): 80B, 16B-aligned, LDS.128 conflict-free
#define THRESH 25.0f       // keep terms with weight ratio > e^-25

__global__ void __launch_bounds__(THREADS, 4) fused_upsample_kernel(
    const float* __restrict__ durations,  // (B, K)
    const float* __restrict__ phoneme,    // (B, D, K)
    const float* __restrict__ frame,      // (B, D, T)
    float* __restrict__ out)              // (B, D, T)
{
    extern __shared__ __align__(16) float sm[];
    float* sC   = sm;                             // KK centers
    float* sW2  = sC + KK;                        // TTILE * WP2  ([t][j] weights)
    float* sPh  = sW2 + TTILE * WP2;              // DHALF * SPANP (also cumsum scratch)
    int*   sKmn = (int*)(sPh + DHALF * SPANP);    // TTILE
    int*   sWid = sKmn + TTILE;                   // TTILE
    int*   sKb  = sWid + TTILE;                   // 2

    const int b     = blockIdx.y;
    const int t0    = blockIdx.x * TTILE;
    const int dbase = blockIdx.z * DHALF;
    const int tid   = threadIdx.x;
    const int lane  = tid & 31;
    const int warp  = tid >> 5;

    // ---- prologue: stage durations, then EXACT sequential fp32 cumsum ----
    for (int i = tid; i < KK; i += THREADS) sPh[i] = durations[b * KK + i];
    if (tid == 0) { sKb[0] = KK; sKb[1] = 0; }
    __syncthreads();
    if (tid == 0) {
        float s = 0.0f;
        #pragma unroll 8
        for (int k = 0; k < KK; ++k) {
            float dk = sPh[k];
            s += dk;                       // strictly sequential association
            sC[k] = s - 0.5f * dk;
        }
    }
    __syncthreads();

    // ---- phase 1: binary-search window + windowed softmax (1 thread / frame) ----
    if (tid < TTILE) {
        const int tt = tid;
        const float tc = (float)(t0 + tt) + 0.5f;
        int pos = 0;                       // count of centers < tc (ascending)
        #pragma unroll
        for (int step = 256; step; step >>= 1) {
            int np = pos + step;
            if (np <= KK && sC[np - 1] < tc) pos = np;
        }
        int ka = pos > 0 ? pos - 1 : 0;
        int kz = pos < KK ? pos : KK - 1;
        float da = fabsf(tc - sC[ka]);
        float db = fabsf(tc - sC[kz]);
        int kc; float dmin;
        if (da <= db) { kc = ka; dmin = da; } else { kc = kz; dmin = db; }
        const float m = -(dmin * dmin);    // max energy (dist^2 unimodal in k)
        const float nthr = m - THRESH;
        int kmn = kc, kmx = kc;
        while (kmn > 0) {                  // qualifying set is contiguous
            float df = tc - sC[kmn - 1];
            if (-(df * df) > nthr) --kmn; else break;
        }
        while (kmx < KK - 1) {
            float df = tc - sC[kmx + 1];
            if (-(df * df) > nthr) ++kmx; else break;
        }
        int wid = kmx - kmn + 1;
        if (wid > WMAX) wid = WMAX;
        float w[WMAX];
        float sum = 0.0f;
        for (int j = 0; j < wid; ++j) {
            float df = tc - sC[kmn + j];
            float x = __expf(-(df * df) - m);
            w[j] = x;
            sum += x;
        }
        const float inv = 1.0f / sum;
        float* wrow = sW2 + tt * WP2;
        #pragma unroll
        for (int j = 0; j < WMAX; ++j)
            wrow[j] = (j < wid) ? w[j] * inv : 0.0f;
        sKmn[tt] = kmn;
        sWid[tt] = wid;
        atomicMin(&sKb[0], kmn);
        atomicMax(&sKb[1], kmx);
    }
    __syncthreads();

    const int kb = sKb[0];
    int span = sKb[1] - kb + 1;
    if (span > SPAN) span = SPAN;          // safety clamp (matches prior passing rounds)

    // ---- phase 2: bulk-stage the block's phoneme panel (coalesced, high MLP) ----
    for (int r = warp; r < DHALF; r += 8) {
        const float* prow = phoneme + ((size_t)b * DD + dbase + r) * KK + kb;
        int c0 = lane, c1 = lane + 32;
        float* dst = sPh + r * SPANP;
        dst[c0] = (c0 < span) ? prow[c0] : 0.0f;
        dst[c1] = (c1 < span) ? prow[c1] : 0.0f;
        if (lane < SPANP - SPAN) dst[SPAN + lane] = 0.0f;   // pad tail
    }
    __syncthreads();

    // ---- phase 3: thread = one t; weights in 16 regs (loaded ONCE); 64 d/warp ----
    const int tl = (warp & 3) * 32 + lane;       // this thread's frame within tile
    const int d0 = (warp >> 2) * (DHALF / 2);    // 64 d-rows per warp
    const int q  = min(sKmn[tl] - kb, SPAN - 1);
    const int wid = sWid[tl];
    const unsigned wm = __reduce_max_sync(0xffffffffu, (unsigned)wid);
    const bool wide = wm > 8;                    // warp-uniform

    const float* wrow = sW2 + tl * WP2;          // 80B rows: LDS.128 conflict-free
    const float4 w0 = *(const float4*)(wrow + 0);
    const float4 w1 = *(const float4*)(wrow + 4);
    const float4 w2 = *(const float4*)(wrow + 8);
    const float4 w3 = *(const float4*)(wrow + 12);

    const size_t fo = ((size_t)b * DD + dbase) * TT + t0 + tl;
    const float* frp = frame + fo;
    float* op = out + fo;

    #pragma unroll 4
    for (int i = 0; i < DHALF / 2; ++i) {
        const int d = d0 + i;
        const float* pr = sPh + d * SPANP + q;
        const float f = frp[(size_t)d * TT];     // scalar, fully coalesced per warp
        float acc;
        acc = w0.x * pr[0];
        acc = fmaf(w0.y, pr[1], acc);
        acc = fmaf(w0.z, pr[2], acc);
        acc = fmaf(w0.w, pr[3], acc);
        acc = fmaf(w1.x, pr[4], acc);
        acc = fmaf(w1.y, pr[5], acc);
        acc = fmaf(w1.z, pr[6], acc);
        acc = fmaf(w1.w, pr[7], acc);
        if (wide) {                              // warp-uniform branch, rare
            acc = fmaf(w2.x, pr[8],  acc);
            acc = fmaf(w2.y, pr[9],  acc);
            acc = fmaf(w2.z, pr[10], acc);
            acc = fmaf(w2.w, pr[11], acc);
            acc = fmaf(w3.x, pr[12], acc);
            acc = fmaf(w3.y, pr[13], acc);
            acc = fmaf(w3.z, pr[14], acc);
            acc = fmaf(w3.w, pr[15], acc);
        }
        op[(size_t)d * TT] = f + acc;
    }
}

extern "C" void kernel_launch(void* const* d_in, const int* in_sizes, int n_in,
                              void* d_out, int out_size) {
    const float* durations = (const float*)d_in[0];  // (B, K)
    const float* phoneme   = (const float*)d_in[1];  // (B, D, K)
    const float* frame     = (const float*)d_in[2];  // (B, D, T)
    float* out = (float*)d_out;                      // (B, D, T)

    size_t smem = (size_t)(KK + TTILE * WP2 + DHALF * SPANP) * sizeof(float)
                + (size_t)(2 * TTILE + 2) * sizeof(int);
    cudaFuncSetAttribute(fused_upsample_kernel,
                         cudaFuncAttributeMaxDynamicSharedMemorySize, (int)smem);
    dim3 grid(TT / TTILE, BB, DD / DHALF);
    fused_upsample_kernel<<<grid, THREADS, smem>>>(durations, phoneme, frame, out);
}

// round 10
// speedup vs baseline: 1.6399x; 1.1244x over previous
#include <cuda_runtime.h>

#define BB 16
#define KK 512
#define DD 256
#define TT 4096
#define TTILE 128          // frames per block
#define DHALF 128          // d-rows per block (D split over grid.z)
#define NWARP 8
#define THREADS 256
#define DPW (DHALF / NWARP)  // 16 d-rows per warp
#define SPAN 64            // max block k-range staged
#define SPANP 80           // sPh row pitch: SPAN + WMAX zero-pad
#define WMAX 16            // max per-frame softmax window kept
#define WP 132             // sW row pitch (floats): 16B multiple + bank offset
#define THRESH 25.0f       // keep terms with weight ratio > e^-25

__global__ void __launch_bounds__(THREADS, 4) fused_upsample_kernel(
    const float* __restrict__ durations,  // (B, K)
    const float* __restrict__ phoneme,    // (B, D, K)
    const float* __restrict__ frame,      // (B, D, T)
    float* __restrict__ out)              // (B, D, T)
{
    extern __shared__ __align__(16) float sm[];
    float* sC  = sm;                              // KK centers
    float* sW  = sC + KK;                         // WMAX * WP   ([j][t] weights)
    float* sPh = sW + WMAX * WP;                  // DHALF * SPANP (also cumsum scratch)
    int* sKmn  = (int*)(sPh + DHALF * SPANP);     // TTILE
    int* sWid  = sKmn + TTILE;                    // TTILE
    int* sKb   = sWid + TTILE;                    // 2

    const int b     = blockIdx.y;
    const int t0    = blockIdx.x * TTILE;
    const int dbase = blockIdx.z * DHALF;
    const int tid   = threadIdx.x;
    const int lane  = tid & 31;
    const int warp  = tid >> 5;

    // ---- prologue: stage durations, EXACT sequential fp32 cumsum (thread 0) ----
    for (int i = tid; i < KK; i += THREADS) sPh[i] = durations[b * KK + i];
    if (tid == 0) { sKb[0] = KK; sKb[1] = 0; }
    for (int i = tid; i < WMAX * WP; i += THREADS) sW[i] = 0.0f;
    __syncthreads();
    if (tid == 0) {
        float s = 0.0f;
        #pragma unroll 8
        for (int k = 0; k < KK; ++k) {
            float dk = sPh[k];
            s += dk;                       // strictly sequential association
            sC[k] = s - 0.5f * dk;
        }
    }
    __syncthreads();

    // ---- phase 1: binary-search window + windowed softmax (1 thread / frame) ----
    if (tid < TTILE) {
        const int tt = tid;
        const float tc = (float)(t0 + tt) + 0.5f;
        int pos = 0;                       // count of centers < tc (ascending)
        #pragma unroll
        for (int step = 256; step; step >>= 1) {
            int np = pos + step;
            if (np <= KK && sC[np - 1] < tc) pos = np;
        }
        int ka = pos > 0 ? pos - 1 : 0;
        int kz = pos < KK ? pos : KK - 1;
        float da = fabsf(tc - sC[ka]);
        float db = fabsf(tc - sC[kz]);
        int kc; float dmin;
        if (da <= db) { kc = ka; dmin = da; } else { kc = kz; dmin = db; }
        const float m = -(dmin * dmin);    // max energy (dist^2 unimodal in k)
        const float nthr = m - THRESH;
        int kmn = kc, kmx = kc;
        while (kmn > 0) {                  // qualifying set is contiguous
            float df = tc - sC[kmn - 1];
            if (-(df * df) > nthr) --kmn; else break;
        }
        while (kmx < KK - 1) {
            float df = tc - sC[kmx + 1];
            if (-(df * df) > nthr) ++kmx; else break;
        }
        int wid = kmx - kmn + 1;
        if (wid > WMAX) wid = WMAX;
        float sum = 0.0f;
        for (int j = 0; j < wid; ++j) {
            float df = tc - sC[kmn + j];
            float x = __expf(-(df * df) - m);
            sW[j * WP + tt] = x;
            sum += x;
        }
        const float inv = 1.0f / sum;
        for (int j = 0; j < wid; ++j) sW[j * WP + tt] *= inv;
        sKmn[tt] = kmn;
        sWid[tt] = wid;
        atomicMin(&sKb[0], kmn);
        atomicMax(&sKb[1], kmx);
    }
    __syncthreads();

    const int kb = sKb[0];
    int span = sKb[1] - kb + 1;
    if (span > SPAN) span = SPAN;          // safety clamp (never triggers here)

    // ---- phase 2: bulk-stage the block's phoneme panel (coalesced, high MLP) ----
    for (int r = warp; r < DHALF; r += NWARP) {
        const float* prow = phoneme + ((size_t)b * DD + dbase + r) * KK + kb;
        int c0 = lane, c1 = lane + 32;
        float* dst = sPh + r * SPANP;
        dst[c0] = (c0 < span) ? prow[c0] : 0.0f;
        dst[c1] = (c1 < span) ? prow[c1] : 0.0f;
        if (lane < SPANP - SPAN) dst[SPAN + lane] = 0.0f;   // pad tail
    }
    __syncthreads();

    // ---- phase 3 (R5-measured winner): float4 streaming, smem weights/phoneme ----
    const int tbase = 4 * lane;
    const int q0 = min(sKmn[tbase + 0] - kb, SPAN - 1);
    const int q1 = min(sKmn[tbase + 1] - kb, SPAN - 1);
    const int q2 = min(sKmn[tbase + 2] - kb, SPAN - 1);
    const int q3 = min(sKmn[tbase + 3] - kb, SPAN - 1);
    const int wm = max(max(sWid[tbase], sWid[tbase + 1]),
                       max(sWid[tbase + 2], sWid[tbase + 3]));

    const int dw = warp * DPW;
    const size_t fo = ((size_t)b * DD + dbase) * TT + t0 + tbase;
    const float* frp = frame + fo;
    float* op = out + fo;

    // depth-2 frame prefetch pipeline
    float4 fA = *(const float4*)(frp + (size_t)dw * TT);
    float4 fB = *(const float4*)(frp + (size_t)(dw + 1) * TT);

    #pragma unroll 1
    for (int i = 0; i < DPW; ++i) {
        const float* pr = sPh + (dw + i) * SPANP;
        float4 fcur = fA;
        fA = fB;
        if (i + 2 < DPW)
            fB = *(const float4*)(frp + (size_t)(dw + i + 2) * TT);

        float sx = 0.0f, sy = 0.0f, sz = 0.0f, sw = 0.0f;
        for (int j = 0; j < wm; ++j) {
            float4 w4 = *(const float4*)(sW + j * WP + tbase);
            sx = fmaf(w4.x, pr[q0 + j], sx);
            sy = fmaf(w4.y, pr[q1 + j], sy);
            sz = fmaf(w4.z, pr[q2 + j], sz);
            sw = fmaf(w4.w, pr[q3 + j], sw);
        }
        *(float4*)(op + (size_t)(dw + i) * TT) =
            make_float4(fcur.x + sx, fcur.y + sy, fcur.z + sz, fcur.w + sw);
    }
}

extern "C" void kernel_launch(void* const* d_in, const int* in_sizes, int n_in,
                              void* d_out, int out_size) {
    const float* durations = (const float*)d_in[0];  // (B, K)
    const float* phoneme   = (const float*)d_in[1];  // (B, D, K)
    const float* frame     = (const float*)d_in[2];  // (B, D, T)
    float* out = (float*)d_out;                      // (B, D, T)

    size_t smem = (size_t)(KK + WMAX * WP + DHALF * SPANP) * sizeof(float)
                + (size_t)(2 * TTILE + 2) * sizeof(int);
    cudaFuncSetAttribute(fused_upsample_kernel,
                         cudaFuncAttributeMaxDynamicSharedMemorySize, (int)smem);
    dim3 grid(TT / TTILE, BB, DD / DHALF);
    fused_upsample_kernel<<<grid, THREADS, smem>>>(durations, phoneme, frame, out);
}